// round 16
// baseline (speedup 1.0000x reference)
#include <cuda_runtime.h>
#include <stdint.h>

#define NP   8192
#define MM   4096
#define BB   4
#define KK   64
#define CIN  64
#define FDIM 67
#define H1D  64
#define H2D  128
#define CAP  512
#define NWORK 72
#define NT   1024
#define NGRP (BB * MM / 4)   // 4096 groups of 4 centroids

// exact same constant the reference compares against: f32(0.2*0.2 in double)
#define R2C ((float)(0.2 * 0.2))

// -------- scratch (device globals; no allocation allowed) --------
__device__ float  g_q[BB * MM * 3];
__device__ int    g_prog[BB];
__device__ float4 g_sort[BB * NP];     // Morton-scatter staging (x,y,z,idx-bits)

// -------- packed f32x2 helpers (per-lane IEEE, bit-identical to scalar) -----
typedef unsigned long long u64;
__device__ __forceinline__ u64 pack2(float lo, float hi) {
    u64 r; asm("mov.b64 %0, {%1, %2};" : "=l"(r) : "f"(lo), "f"(hi)); return r;
}
__device__ __forceinline__ void unpack2(u64 v, float& lo, float& hi) {
    asm("mov.b64 {%0, %1}, %2;" : "=f"(lo), "=f"(hi) : "l"(v));
}
__device__ __forceinline__ u64 add2(u64 a, u64 b) {
    u64 r; asm("add.rn.f32x2 %0, %1, %2;" : "=l"(r) : "l"(a), "l"(b)); return r;
}
__device__ __forceinline__ u64 mul2(u64 a, u64 b) {
    u64 r; asm("mul.rn.f32x2 %0, %1, %2;" : "=l"(r) : "l"(a), "l"(b)); return r;
}
__device__ __forceinline__ u64 fma2(u64 a, u64 b, u64 c) {
    u64 r; asm("fma.rn.f32x2 %0, %1, %2, %3;" : "=l"(r) : "l"(a), "l"(b), "l"(c)); return r;
}
__device__ __forceinline__ unsigned redux_max(unsigned v) {
    unsigned r; asm("redux.sync.max.u32 %0, %1, 0xffffffff;" : "=r"(r) : "r"(v)); return r;
}
__device__ __forceinline__ u64 shfl_xor64(u64 v, int m) {
    unsigned lo = (unsigned)v, hi = (unsigned)(v >> 32);
    lo = __shfl_xor_sync(0xffffffffu, lo, m);
    hi = __shfl_xor_sync(0xffffffffu, hi, m);
    return ((u64)hi << 32) | (u64)lo;
}
__device__ __forceinline__ int spread3(int v) {
    return (v & 1) | ((v & 2) << 2) | ((v & 4) << 4);
}
__device__ __forceinline__ int cell_of(float px, float py, float pz) {
    int cx = min(7, max(0, (int)(px * 8.0f)));
    int cy = min(7, max(0, (int)(py * 8.0f)));
    int cz = min(7, max(0, (int)(pz * 8.0f)));
    return spread3(cx) | (spread3(cy) << 1) | (spread3(cz) << 2);
}

__global__ void reset_kernel() {
    if (threadIdx.x < BB) g_prog[threadIdx.x] = 0;
}

// =====================================================================
// Fused persistent kernel, 1024 threads/block.
// Blocks 0..3: FPS producer — 32 warps x 256 Morton points (8 pts/thread):
//   finer warp-granular bbox skip + halved active-warp update issue.
//   Two-bar reduction with atomicMin original-index tie-break (exact).
// Blocks 4..75: workers — 4-centroid batched radius scan, bitonic top-K
//   (512 keys, upper 512 threads carry sentinels through barriers),
//   one-pass float4 gather, FFMA2 MLP (retiled for low reg pressure),
//   masked max.
// =====================================================================
__global__ void __launch_bounds__(NT, 1) fused_kernel(
    const float* __restrict__ x, const float* __restrict__ pos,
    const float* __restrict__ W1, const float* __restrict__ b1,
    const float* __restrict__ W2, const float* __restrict__ b2,
    float* __restrict__ out, int out_size)
{
    extern __shared__ float smf[];
    const int tid = threadIdx.x;

    if (blockIdx.x < BB) {
        // ======================= FPS producer =======================
        float* sxo = smf;                 // [NP] original order
        float* syo = smf + NP;
        float* szo = smf + 2 * NP;
        int* cnt = (int*)(smf + 3 * NP);  // [512]

        __shared__ unsigned rv[32];
        __shared__ int wsum[16];
        __shared__ int s_widx[2];

        const int b = blockIdx.x;
        const int lane = tid & 31, warp = tid >> 5;
        const float* pb = pos + (size_t)b * NP * 3;

        if (tid < 512) cnt[tid] = 0;
        if (tid == 0) { s_widx[0] = 0x7FFFFFFF; s_widx[1] = 0x7FFFFFFF; }
        __syncthreads();
        for (int i = tid; i < NP; i += NT) {
            float px = pb[3 * i + 0], py = pb[3 * i + 1], pz = pb[3 * i + 2];
            sxo[i] = px; syo[i] = py; szo[i] = pz;
            atomicAdd(&cnt[cell_of(px, py, pz)], 1);
        }
        __syncthreads();

        // exclusive prefix sum over 512 cells (threads 0..511)
        int myc = 0, v = 0;
        if (tid < 512) {
            myc = cnt[tid];
            v = myc;
#pragma unroll
            for (int o = 1; o < 32; o <<= 1) {
                int n = __shfl_up_sync(0xffffffffu, v, o);
                if (lane >= o) v += n;
            }
            if (lane == 31) wsum[warp] = v;
        }
        __syncthreads();
        if (tid < 512) {
            int woff = 0;
#pragma unroll
            for (int j = 0; j < 16; j++) woff += (j < warp) ? wsum[j] : 0;
            cnt[tid] = woff + v - myc;
        }
        __syncthreads();

        // scatter into Morton order -> GLOBAL scratch (one-time)
        for (int i = tid; i < NP; i += NT) {
            float px = sxo[i], py = syo[i], pz = szo[i];
            int slot = atomicAdd(&cnt[cell_of(px, py, pz)], 1);
            float4 rec; rec.x = px; rec.y = py; rec.z = pz; rec.w = __int_as_float(i);
            g_sort[b * NP + slot] = rec;
        }
        __syncthreads();   // global writes visible block-wide after bar

        const int base = tid * 8;
        u64 X[4], Y[4], Z[4];
        unsigned idx2[4];
        float lox = 1e30f, loy = 1e30f, loz = 1e30f;
        float hix = -1e30f, hiy = -1e30f, hiz = -1e30f;
#pragma unroll
        for (int i = 0; i < 4; i++) {
            float4 v0 = g_sort[b * NP + base + 2 * i];
            float4 v1 = g_sort[b * NP + base + 2 * i + 1];
            X[i] = pack2(v0.x, v1.x); Y[i] = pack2(v0.y, v1.y); Z[i] = pack2(v0.z, v1.z);
            idx2[i] = (__float_as_uint(v0.w) & 0xFFFFu) | (__float_as_uint(v1.w) << 16);
            lox = fminf(lox, fminf(v0.x, v1.x)); hix = fmaxf(hix, fmaxf(v0.x, v1.x));
            loy = fminf(loy, fminf(v0.y, v1.y)); hiy = fmaxf(hiy, fmaxf(v0.y, v1.y));
            loz = fminf(loz, fminf(v0.z, v1.z)); hiz = fmaxf(hiz, fmaxf(v0.z, v1.z));
        }

        float cx = sxo[0], cy = syo[0], cz = szo[0];
        float d[8];
        float tv = -1.0f;
        {
            u64 ncx = pack2(-cx, -cx), ncy = pack2(-cy, -cy), ncz = pack2(-cz, -cz);
#pragma unroll
            for (int i = 0; i < 4; i++) {
                u64 dx = add2(X[i], ncx);
                u64 dy = add2(Y[i], ncy);
                u64 dz = add2(Z[i], ncz);
                u64 nd = mul2(dx, dx);
                nd = fma2(dy, dy, nd);
                nd = fma2(dz, dz, nd);
                float n0, n1; unpack2(nd, n0, n1);
                d[2 * i + 0] = n0;
                d[2 * i + 1] = n1;
                tv = fmaxf(tv, fmaxf(n0, n1));
            }
        }
        if (tid == 0) {
            g_q[(b * MM) * 3 + 0] = cx;
            g_q[(b * MM) * 3 + 1] = cy;
            g_q[(b * MM) * 3 + 2] = cz;
        }

        for (int t = 1; t < MM; t++) {
            // block max of tv via u32 redux (d2 >= 0 -> bit order == float order)
            const unsigned tb = __float_as_uint(tv);
            unsigned wmax = redux_max(tb);
            if (lane == 0) rv[warp] = wmax;
            __syncthreads();                                  // (A)

            // depth-5 scalar max tree over 32 warp maxima
            unsigned c0 = max(rv[0],  rv[1]),  c1 = max(rv[2],  rv[3]);
            unsigned c2 = max(rv[4],  rv[5]),  c3 = max(rv[6],  rv[7]);
            unsigned c4 = max(rv[8],  rv[9]),  c5 = max(rv[10], rv[11]);
            unsigned c6 = max(rv[12], rv[13]), c7 = max(rv[14], rv[15]);
            unsigned c8 = max(rv[16], rv[17]), c9 = max(rv[18], rv[19]);
            unsigned ca = max(rv[20], rv[21]), cb = max(rv[22], rv[23]);
            unsigned cc2 = max(rv[24], rv[25]), cd = max(rv[26], rv[27]);
            unsigned ce = max(rv[28], rv[29]), cf = max(rv[30], rv[31]);
            unsigned e0 = max(max(c0, c1), max(c2, c3));
            unsigned e1 = max(max(c4, c5), max(c6, c7));
            unsigned e2 = max(max(c8, c9), max(ca, cb));
            unsigned e3 = max(max(cc2, cd), max(ce, cf));
            const unsigned vmb = max(max(e0, e1), max(e2, e3));
            const float vm = __uint_as_float(vmb);

            const int cur = t & 1;
            if (tb == vmb) {                                  // only potential winners
#pragma unroll
                for (int i = 0; i < 8; i++)
                    if (d[i] == vm) {
                        int orig = (int)((idx2[i >> 1] >> ((i & 1) * 16)) & 0xFFFFu);
                        atomicMin(&s_widx[cur], orig);        // reference tie-break
                    }
            }
            if (tid == 0) s_widx[cur ^ 1] = 0x7FFFFFFF;       // pre-reset other buffer
            __syncthreads();                                  // (B)

            const int w = s_widx[cur];                        // original index
            cx = sxo[w]; cy = syo[w]; cz = szo[w];
            if (tid == 0) {
                g_q[(b * MM + t) * 3 + 0] = cx;
                g_q[(b * MM + t) * 3 + 1] = cy;
                g_q[(b * MM + t) * 3 + 2] = cz;
                if ((t & 15) == 15 || t == MM - 1) {
                    __threadfence();
                    *(volatile int*)&g_prog[b] = t + 1;
                }
            }

            // bbox lower-bound distance: skip update if it can't lower any d
            float ddx = fmaxf(fmaxf(lox - cx, cx - hix), 0.0f);
            float ddy = fmaxf(fmaxf(loy - cy, cy - hiy), 0.0f);
            float ddz = fmaxf(fmaxf(loz - cz, cz - hiz), 0.0f);
            float dm2 = ddx * ddx;
            dm2 = fmaf(ddy, ddy, dm2);
            dm2 = fmaf(ddz, ddz, dm2);

            if (dm2 * 0.99999f < tv) {
                u64 ncx = pack2(-cx, -cx), ncy = pack2(-cy, -cy), ncz = pack2(-cz, -cz);
                float ntv = -1.0f;
#pragma unroll
                for (int i = 0; i < 4; i++) {
                    u64 dx = add2(X[i], ncx);
                    u64 dy = add2(Y[i], ncy);
                    u64 dz = add2(Z[i], ncz);
                    u64 nd = mul2(dx, dx);
                    nd = fma2(dy, dy, nd);
                    nd = fma2(dz, dz, nd);
                    float n0, n1; unpack2(nd, n0, n1);
                    float d0 = fminf(d[2 * i + 0], n0);
                    float d1 = fminf(d[2 * i + 1], n1);
                    d[2 * i + 0] = d0;
                    d[2 * i + 1] = d1;
                    ntv = fmaxf(ntv, fmaxf(d0, d1));
                }
                tv = ntv;
            }
        }
        return;
    }

    // ======================= worker =======================
    float* W1s  = smf;               // 67*64 = 4288
    float* b1s  = smf + 4288;        // 64
    float* W2s  = smf + 4352;        // 64*128 = 8192
    float* b2s  = smf + 12544;       // 128
    float* feat = smf + 12672;       // 64*68 = 4352
    float* h1s  = smf + 17024;       // 64*68 = 4352
    float* pmax = smf + 21376;       // 32*128 = 4096
    u64*   keys4 = (u64*)(smf + 25472);  // 4 x 512 u64 = 16KB -> ends 118272B

    __shared__ float qs[4][3];
    __shared__ int cnt8[2][4];

    for (int i = tid; i < FDIM * H1D; i += NT) W1s[i] = W1[i];
    for (int i = tid; i < H1D * H2D; i += NT) W2s[i] = W2[i];
    if (tid < H1D) b1s[tid] = b1[tid];
    if (tid < H2D) b2s[tid] = b2[tid];
    if (tid < 8) cnt8[tid >> 2][tid & 3] = 0;

    const int wb = (int)blockIdx.x - BB;
    const int b = wb & 3;                        // fixed cloud per block (72 % 4 == 0)
    const float* pb = pos + (size_t)b * NP * 3;
    const float4* xb4 = (const float4*)(x + (size_t)b * NP * CIN);
    int kk = 0;
    for (int g = wb; g < NGRP; g += NWORK, kk++) {
        const int tbase = (g >> 2) * 4;          // 4 consecutive centroids of cloud b
        const int par = kk & 1;

        if (tid == 0) {
            while (*(volatile int*)&g_prog[b] < tbase + 4) { }
            __threadfence();
#pragma unroll
            for (int cc = 0; cc < 4; cc++) {
                int c = b * MM + tbase + cc;
                qs[cc][0] = __ldcg(&g_q[c * 3 + 0]);
                qs[cc][1] = __ldcg(&g_q[c * 3 + 1]);
                qs[cc][2] = __ldcg(&g_q[c * 3 + 2]);
            }
        }
        __syncthreads();                              // A
        const float q0x = qs[0][0], q0y = qs[0][1], q0z = qs[0][2];
        const float q1x = qs[1][0], q1y = qs[1][1], q1z = qs[1][2];
        const float q2x = qs[2][0], q2y = qs[2][1], q2z = qs[2][2];
        const float q3x = qs[3][0], q3y = qs[3][1], q3z = qs[3][2];

        // -------- shared radius scan: 1 pass of pos, 4 centroids --------
        int* cntp = &cnt8[par][0];
#pragma unroll 4
        for (int u = 0; u < 8; u++) {
            int p = tid + NT * u;
            float px = pb[3 * p + 0], py = pb[3 * p + 1], pz = pb[3 * p + 2];
            {
                float dx = q0x - px, dy = q0y - py, dz = q0z - pz;
                float d2 = dx * dx + dy * dy + dz * dz;
                if (d2 <= R2C) { int s = atomicAdd(&cntp[0], 1);
                    if (s < CAP) keys4[0 * CAP + s] = ((u64)__float_as_uint(d2) << 32) | (unsigned)p; }
            }
            {
                float dx = q1x - px, dy = q1y - py, dz = q1z - pz;
                float d2 = dx * dx + dy * dy + dz * dz;
                if (d2 <= R2C) { int s = atomicAdd(&cntp[1], 1);
                    if (s < CAP) keys4[1 * CAP + s] = ((u64)__float_as_uint(d2) << 32) | (unsigned)p; }
            }
            {
                float dx = q2x - px, dy = q2y - py, dz = q2z - pz;
                float d2 = dx * dx + dy * dy + dz * dz;
                if (d2 <= R2C) { int s = atomicAdd(&cntp[2], 1);
                    if (s < CAP) keys4[2 * CAP + s] = ((u64)__float_as_uint(d2) << 32) | (unsigned)p; }
            }
            {
                float dx = q3x - px, dy = q3y - py, dz = q3z - pz;
                float d2 = dx * dx + dy * dy + dz * dz;
                if (d2 <= R2C) { int s = atomicAdd(&cntp[3], 1);
                    if (s < CAP) keys4[3 * CAP + s] = ((u64)__float_as_uint(d2) << 32) | (unsigned)p; }
            }
        }
        __syncthreads();                              // B
        if (tid < 4) cnt8[par ^ 1][tid] = 0;          // reset other buffer

        // -------- per centroid: sort + gather + MLP + outputs --------
        for (int cc = 0; cc < 4; cc++) {
            const int c = b * MM + tbase + cc;
            const int n = min(cnt8[par][cc], CAP);
            u64* keyc = keys4 + cc * CAP;

            // bitonic sort, 512 keys ascending; threads >=512 carry sentinels
            u64 key = (tid < n) ? keyc[tid] : 0xFFFFFFFFFFFFFFFFull;
#pragma unroll
            for (int k2 = 2; k2 <= CAP; k2 <<= 1) {
#pragma unroll
                for (int j = k2 >> 1; j > 0; j >>= 1) {
                    const bool asc = ((tid & k2) == 0);
                    u64 other;
                    if (j >= 32) {
                        __syncthreads();
                        if (tid < CAP) keyc[tid] = key;
                        __syncthreads();
                        other = (tid < CAP) ? keyc[tid ^ j] : key;
                    } else {
                        other = shfl_xor64(key, j);
                    }
                    const bool lower = ((tid & j) == 0);
                    const bool keepMin = (lower == asc);
                    const bool less = key < other;
                    key = (less == keepMin) ? key : other;
                }
            }
            __syncthreads();
            if (tid < CAP) keyc[tid] = key;
            __syncthreads();                          // C
            const int m = min(n, KK);

            // gather features (float4, one pass: 1024 threads = 64x16)
            {
                int j = tid >> 4, c4 = tid & 15;
                int row = (j < m) ? (int)(keyc[j] & 0xFFFFFFFFull) : 0;
                float4 vv = xb4[(size_t)row * 16 + c4];
                if (j >= m) { vv.x = 0.0f; vv.y = 0.0f; vv.z = 0.0f; vv.w = 0.0f; }
                *(float4*)&feat[j * 68 + c4 * 4] = vv;
            }
            if (tid < KK) {
                int j = tid;
                int row = (j < m) ? (int)(keyc[j] & 0xFFFFFFFFull) : 0;
                const float* pr = pb + (size_t)row * 3;
                feat[j * 68 + 64] = (j < m) ? pr[0] - qs[cc][0] : 0.0f;
                feat[j * 68 + 65] = (j < m) ? pr[1] - qs[cc][1] : 0.0f;
                feat[j * 68 + 66] = (j < m) ? pr[2] - qs[cc][2] : 0.0f;
                feat[j * 68 + 67] = 0.0f;
            }
            __syncthreads();                          // D

            // phase 1: h1[64,64] = relu(feat @ W1 + b1), 1 row x 4 cols/thread
            {
                const int row = tid >> 4;             // 0..63
                const int cg = tid & 15;              // cols cg*4
                float4 bv = *(const float4*)&b1s[cg * 4];
                u64 ap = pack2(bv.x, bv.y), aq = pack2(bv.z, bv.w);
                const float* fp = &feat[row * 68];
                for (int k = 0; k < FDIM; k++) {
                    float f0 = fp[k];
                    float4 w = *(const float4*)&W1s[k * 64 + cg * 4];
                    u64 w01 = pack2(w.x, w.y), w23 = pack2(w.z, w.w);
                    u64 fv = pack2(f0, f0);
                    ap = fma2(fv, w01, ap); aq = fma2(fv, w23, aq);
                }
                float v0, v1, v2, v3;
                float4 h;
                unpack2(ap, v0, v1); unpack2(aq, v2, v3);
                h.x = fmaxf(v0, 0.0f); h.y = fmaxf(v1, 0.0f);
                h.z = fmaxf(v2, 0.0f); h.w = fmaxf(v3, 0.0f);
                *(float4*)&h1s[row * 68 + cg * 4] = h;
            }
            __syncthreads();                          // E

            // phase 2: relu(h1 @ W2 + b2), 2 rows x 4 cols/thread, masked max
            {
                const int rg = tid >> 5;              // 0..31 -> rows rg*2, rg*2+1
                const int cg = tid & 31;              // cols cg*4
                float4 bv = *(const float4*)&b2s[cg * 4];
                u64 a0p = pack2(bv.x, bv.y), a0q = pack2(bv.z, bv.w);
                u64 a1p = a0p, a1q = a0q;
                const float* h0p = &h1s[(rg * 2 + 0) * 68];
                const float* h1p = &h1s[(rg * 2 + 1) * 68];
                for (int k = 0; k < H1D; k++) {
                    float4 w = *(const float4*)&W2s[k * 128 + cg * 4];
                    u64 w01 = pack2(w.x, w.y), w23 = pack2(w.z, w.w);
                    float h0 = h0p[k], h1v = h1p[k];
                    u64 h0v = pack2(h0, h0), h1vv = pack2(h1v, h1v);
                    a0p = fma2(h0v, w01, a0p); a0q = fma2(h0v, w23, a0q);
                    a1p = fma2(h1vv, w01, a1p); a1q = fma2(h1vv, w23, a1q);
                }
                float mx0 = -3.402823466e38f, mx1 = mx0, mx2 = mx0, mx3 = mx0;
                if (rg * 2 + 0 < m) {
                    float v0, v1, v2, v3;
                    unpack2(a0p, v0, v1); unpack2(a0q, v2, v3);
                    mx0 = fmaxf(mx0, fmaxf(v0, 0.0f));
                    mx1 = fmaxf(mx1, fmaxf(v1, 0.0f));
                    mx2 = fmaxf(mx2, fmaxf(v2, 0.0f));
                    mx3 = fmaxf(mx3, fmaxf(v3, 0.0f));
                }
                if (rg * 2 + 1 < m) {
                    float v0, v1, v2, v3;
                    unpack2(a1p, v0, v1); unpack2(a1q, v2, v3);
                    mx0 = fmaxf(mx0, fmaxf(v0, 0.0f));
                    mx1 = fmaxf(mx1, fmaxf(v1, 0.0f));
                    mx2 = fmaxf(mx2, fmaxf(v2, 0.0f));
                    mx3 = fmaxf(mx3, fmaxf(v3, 0.0f));
                }
                float4 mv; mv.x = mx0; mv.y = mx1; mv.z = mx2; mv.w = mx3;
                *(float4*)&pmax[rg * 128 + cg * 4] = mv;
            }
            __syncthreads();                          // F

            if (tid < H2D) {
                float r = pmax[tid];
#pragma unroll
                for (int gg = 1; gg < 32; gg++) r = fmaxf(r, pmax[gg * 128 + tid]);
                if (c * H2D + tid < out_size) out[c * H2D + tid] = r;
            }
            {
                const int PO = BB * MM * H2D;
                const int BO = PO + BB * MM * 3;
                if (tid >= 128 && tid < 131) {
                    int k3 = tid - 128;
                    if (PO + c * 3 + k3 < out_size) out[PO + c * 3 + k3] = qs[cc][k3];
                }
                if (tid == 131 && BO + c < out_size) out[BO + c] = (float)b;
            }
            __syncthreads();                          // G (smem reuse next centroid)
        }
    }
}

// =====================================================================
extern "C" void kernel_launch(void* const* d_in, const int* in_sizes, int n_in,
                              void* d_out, int out_size)
{
    const float* x   = (const float*)d_in[0];
    const float* pos = (const float*)d_in[1];
    const float* W1  = (const float*)d_in[3];
    const float* b1  = (const float*)d_in[4];
    const float* W2  = (const float*)d_in[5];
    const float* b2  = (const float*)d_in[6];
    float* out = (float*)d_out;

    const int FUSED_SMEM = 118272;   // worker layout is the max (keys4 ends at 118272B)
    cudaFuncSetAttribute(fused_kernel, cudaFuncAttributeMaxDynamicSharedMemorySize, FUSED_SMEM);

    reset_kernel<<<1, 32>>>();
    fused_kernel<<<BB + NWORK, NT, FUSED_SMEM>>>(x, pos, W1, b1, W2, b2, out, out_size);
}

// round 17
// speedup vs baseline: 1.4903x; 1.4903x over previous
#include <cuda_runtime.h>
#include <stdint.h>

#define NP   8192
#define MM   4096
#define BB   4
#define KK   64
#define CIN  64
#define FDIM 67
#define H1D  64
#define H2D  128
#define CAP  512
#define NWORK 144
#define NGRP (BB * MM / 4)   // 4096 groups of 4 centroids

// exact same constant the reference compares against: f32(0.2*0.2 in double)
#define R2C ((float)(0.2 * 0.2))

// -------- scratch (device globals; no allocation allowed) --------
__device__ float  g_q[BB * MM * 3];
__device__ int    g_prog[BB];
__device__ float4 g_sort[BB * NP];     // Morton-scatter staging (x,y,z,idx-bits)

// -------- packed f32x2 helpers (per-lane IEEE, bit-identical to scalar) -----
typedef unsigned long long u64;
__device__ __forceinline__ u64 pack2(float lo, float hi) {
    u64 r; asm("mov.b64 %0, {%1, %2};" : "=l"(r) : "f"(lo), "f"(hi)); return r;
}
__device__ __forceinline__ void unpack2(u64 v, float& lo, float& hi) {
    asm("mov.b64 {%0, %1}, %2;" : "=f"(lo), "=f"(hi) : "l"(v));
}
__device__ __forceinline__ u64 add2(u64 a, u64 b) {
    u64 r; asm("add.rn.f32x2 %0, %1, %2;" : "=l"(r) : "l"(a), "l"(b)); return r;
}
__device__ __forceinline__ u64 mul2(u64 a, u64 b) {
    u64 r; asm("mul.rn.f32x2 %0, %1, %2;" : "=l"(r) : "l"(a), "l"(b)); return r;
}
__device__ __forceinline__ u64 fma2(u64 a, u64 b, u64 c) {
    u64 r; asm("fma.rn.f32x2 %0, %1, %2, %3;" : "=l"(r) : "l"(a), "l"(b), "l"(c)); return r;
}
__device__ __forceinline__ unsigned redux_max(unsigned v) {
    unsigned r; asm("redux.sync.max.u32 %0, %1, 0xffffffff;" : "=r"(r) : "r"(v)); return r;
}
__device__ __forceinline__ u64 shfl_xor64(u64 v, int m) {
    unsigned lo = (unsigned)v, hi = (unsigned)(v >> 32);
    lo = __shfl_xor_sync(0xffffffffu, lo, m);
    hi = __shfl_xor_sync(0xffffffffu, hi, m);
    return ((u64)hi << 32) | (u64)lo;
}
__device__ __forceinline__ int spread3(int v) {
    return (v & 1) | ((v & 2) << 2) | ((v & 4) << 4);
}
__device__ __forceinline__ int cell_of(float px, float py, float pz) {
    int cx = min(7, max(0, (int)(px * 8.0f)));
    int cy = min(7, max(0, (int)(py * 8.0f)));
    int cz = min(7, max(0, (int)(pz * 8.0f)));
    return spread3(cx) | (spread3(cy) << 1) | (spread3(cz) << 2);
}

__global__ void reset_kernel() {
    if (threadIdx.x < BB) g_prog[threadIdx.x] = 0;
}

// =====================================================================
// Fused persistent kernel (best-measured configuration, 2564us).
// Blocks 0..3: FPS producer (two-bar reduction, atomicMin tie-break —
//   the best-measured variant), publishing g_prog every 16 steps.
// Blocks 4..147: workers — each iteration handles FOUR consecutive
//   centroids of its cloud: one shared radius scan (pos loads amortized
//   4x), then per centroid: register/shfl bitonic top-K, float4 gather,
//   FFMA2 MLP, masked max.
// =====================================================================
__global__ void __launch_bounds__(512, 1) fused_kernel(
    const float* __restrict__ x, const float* __restrict__ pos,
    const float* __restrict__ W1, const float* __restrict__ b1,
    const float* __restrict__ W2, const float* __restrict__ b2,
    float* __restrict__ out, int out_size)
{
    extern __shared__ float smf[];
    const int tid = threadIdx.x;

    if (blockIdx.x < BB) {
        // ======================= FPS producer =======================
        float* sxo = smf;                 // [NP] original order
        float* syo = smf + NP;
        float* szo = smf + 2 * NP;
        int* cnt = (int*)(smf + 3 * NP);  // [512]

        __shared__ unsigned rv[16];
        __shared__ int wsum[16];
        __shared__ int s_widx[2];

        const int b = blockIdx.x;
        const int lane = tid & 31, warp = tid >> 5;
        const float* pb = pos + (size_t)b * NP * 3;

        cnt[tid] = 0;
        if (tid == 0) { s_widx[0] = 0x7FFFFFFF; s_widx[1] = 0x7FFFFFFF; }
        __syncthreads();
        for (int i = tid; i < NP; i += 512) {
            float px = pb[3 * i + 0], py = pb[3 * i + 1], pz = pb[3 * i + 2];
            sxo[i] = px; syo[i] = py; szo[i] = pz;
            atomicAdd(&cnt[cell_of(px, py, pz)], 1);
        }
        __syncthreads();

        int myc = cnt[tid];
        int v = myc;
#pragma unroll
        for (int o = 1; o < 32; o <<= 1) {
            int n = __shfl_up_sync(0xffffffffu, v, o);
            if (lane >= o) v += n;
        }
        if (lane == 31) wsum[warp] = v;
        __syncthreads();
        int woff = 0;
#pragma unroll
        for (int j = 0; j < 16; j++) woff += (j < warp) ? wsum[j] : 0;
        const int start = woff + v - myc;
        __syncthreads();
        cnt[tid] = start;
        __syncthreads();

        // scatter into Morton order -> GLOBAL scratch (one-time)
        for (int i = tid; i < NP; i += 512) {
            float px = sxo[i], py = syo[i], pz = szo[i];
            int slot = atomicAdd(&cnt[cell_of(px, py, pz)], 1);
            float4 rec; rec.x = px; rec.y = py; rec.z = pz; rec.w = __int_as_float(i);
            g_sort[b * NP + slot] = rec;
        }
        __syncthreads();   // global writes visible block-wide after bar

        const int base = tid * 16;
        u64 X[8], Y[8], Z[8];
        unsigned idx2[8];
        float lox = 1e30f, loy = 1e30f, loz = 1e30f;
        float hix = -1e30f, hiy = -1e30f, hiz = -1e30f;
#pragma unroll
        for (int i = 0; i < 8; i++) {
            float4 v0 = g_sort[b * NP + base + 2 * i];
            float4 v1 = g_sort[b * NP + base + 2 * i + 1];
            X[i] = pack2(v0.x, v1.x); Y[i] = pack2(v0.y, v1.y); Z[i] = pack2(v0.z, v1.z);
            idx2[i] = (__float_as_uint(v0.w) & 0xFFFFu) | (__float_as_uint(v1.w) << 16);
            lox = fminf(lox, fminf(v0.x, v1.x)); hix = fmaxf(hix, fmaxf(v0.x, v1.x));
            loy = fminf(loy, fminf(v0.y, v1.y)); hiy = fmaxf(hiy, fmaxf(v0.y, v1.y));
            loz = fminf(loz, fminf(v0.z, v1.z)); hiz = fmaxf(hiz, fmaxf(v0.z, v1.z));
        }

        float cx = sxo[0], cy = syo[0], cz = szo[0];
        float d[16];
        float tv = -1.0f;
        {
            u64 ncx = pack2(-cx, -cx), ncy = pack2(-cy, -cy), ncz = pack2(-cz, -cz);
#pragma unroll
            for (int i = 0; i < 8; i++) {
                u64 dx = add2(X[i], ncx);
                u64 dy = add2(Y[i], ncy);
                u64 dz = add2(Z[i], ncz);
                u64 nd = mul2(dx, dx);
                nd = fma2(dy, dy, nd);
                nd = fma2(dz, dz, nd);
                float n0, n1; unpack2(nd, n0, n1);
                d[2 * i + 0] = n0;
                d[2 * i + 1] = n1;
                tv = fmaxf(tv, fmaxf(n0, n1));
            }
        }
        if (tid == 0) {
            g_q[(b * MM) * 3 + 0] = cx;
            g_q[(b * MM) * 3 + 1] = cy;
            g_q[(b * MM) * 3 + 2] = cz;
        }

        for (int t = 1; t < MM; t++) {
            // block max of tv via u32 redux (d2 >= 0 -> bit order == float order)
            const unsigned tb = __float_as_uint(tv);
            unsigned wmax = redux_max(tb);
            if (lane == 0) rv[warp] = wmax;
            __syncthreads();                                  // (A)

            unsigned vmb = rv[0];
#pragma unroll
            for (int j = 1; j < 16; j++) vmb = max(vmb, rv[j]);
            const float vm = __uint_as_float(vmb);

            const int cur = t & 1;
            if (tb == vmb) {                                  // only potential winners
#pragma unroll
                for (int i = 0; i < 16; i++)
                    if (d[i] == vm) {
                        int orig = (int)((idx2[i >> 1] >> ((i & 1) * 16)) & 0xFFFFu);
                        atomicMin(&s_widx[cur], orig);        // reference tie-break
                    }
            }
            if (tid == 0) s_widx[cur ^ 1] = 0x7FFFFFFF;       // pre-reset other buffer
            __syncthreads();                                  // (B)

            const int w = s_widx[cur];                        // original index
            cx = sxo[w]; cy = syo[w]; cz = szo[w];
            if (tid == 0) {
                g_q[(b * MM + t) * 3 + 0] = cx;
                g_q[(b * MM + t) * 3 + 1] = cy;
                g_q[(b * MM + t) * 3 + 2] = cz;
                if ((t & 15) == 15 || t == MM - 1) {
                    __threadfence();
                    *(volatile int*)&g_prog[b] = t + 1;
                }
            }

            // bbox lower-bound distance: skip update if it can't lower any d
            float ddx = fmaxf(fmaxf(lox - cx, cx - hix), 0.0f);
            float ddy = fmaxf(fmaxf(loy - cy, cy - hiy), 0.0f);
            float ddz = fmaxf(fmaxf(loz - cz, cz - hiz), 0.0f);
            float dm2 = ddx * ddx;
            dm2 = fmaf(ddy, ddy, dm2);
            dm2 = fmaf(ddz, ddz, dm2);

            if (dm2 * 0.99999f < tv) {
                u64 ncx = pack2(-cx, -cx), ncy = pack2(-cy, -cy), ncz = pack2(-cz, -cz);
                float ntv = -1.0f;
#pragma unroll
                for (int i = 0; i < 8; i++) {
                    u64 dx = add2(X[i], ncx);
                    u64 dy = add2(Y[i], ncy);
                    u64 dz = add2(Z[i], ncz);
                    u64 nd = mul2(dx, dx);
                    nd = fma2(dy, dy, nd);
                    nd = fma2(dz, dz, nd);
                    float n0, n1; unpack2(nd, n0, n1);
                    float d0 = fminf(d[2 * i + 0], n0);
                    float d1 = fminf(d[2 * i + 1], n1);
                    d[2 * i + 0] = d0;
                    d[2 * i + 1] = d1;
                    ntv = fmaxf(ntv, fmaxf(d0, d1));
                }
                tv = ntv;
            }
        }
        return;
    }

    // ======================= worker =======================
    float* W1s  = smf;               // 67*64 = 4288
    float* b1s  = smf + 4288;        // 64
    float* W2s  = smf + 4352;        // 64*128 = 8192
    float* b2s  = smf + 12544;       // 128
    float* feat = smf + 12672;       // 64*68 = 4352
    float* h1s  = smf + 17024;       // 64*68 = 4352
    float* pmax = smf + 21376;       // 16*128 = 2048
    u64*   keys4 = (u64*)(smf + 23424);  // 4 x 512 u64 = 16KB -> ends 110080B

    __shared__ float qs[4][3];
    __shared__ int cnt8[2][4];

    for (int i = tid; i < FDIM * H1D; i += 512) W1s[i] = W1[i];
    for (int i = tid; i < H1D * H2D; i += 512) W2s[i] = W2[i];
    if (tid < H1D) b1s[tid] = b1[tid];
    if (tid < H2D) b2s[tid] = b2[tid];
    if (tid < 8) cnt8[tid >> 2][tid & 3] = 0;

    const int wb = (int)blockIdx.x - BB;
    const int b = wb & 3;                        // fixed cloud per block (144 % 4 == 0)
    const float* pb = pos + (size_t)b * NP * 3;
    const float4* xb4 = (const float4*)(x + (size_t)b * NP * CIN);
    int kk = 0;
    for (int g = wb; g < NGRP; g += NWORK, kk++) {
        const int tbase = (g >> 2) * 4;          // 4 consecutive centroids of cloud b
        const int par = kk & 1;

        if (tid == 0) {
            while (*(volatile int*)&g_prog[b] < tbase + 4) { }
            __threadfence();
#pragma unroll
            for (int cc = 0; cc < 4; cc++) {
                int c = b * MM + tbase + cc;
                qs[cc][0] = __ldcg(&g_q[c * 3 + 0]);
                qs[cc][1] = __ldcg(&g_q[c * 3 + 1]);
                qs[cc][2] = __ldcg(&g_q[c * 3 + 2]);
            }
        }
        __syncthreads();                              // A
        const float q0x = qs[0][0], q0y = qs[0][1], q0z = qs[0][2];
        const float q1x = qs[1][0], q1y = qs[1][1], q1z = qs[1][2];
        const float q2x = qs[2][0], q2y = qs[2][1], q2z = qs[2][2];
        const float q3x = qs[3][0], q3y = qs[3][1], q3z = qs[3][2];

        // -------- shared radius scan: 1 pass of pos, 4 centroids --------
        int* cntp = &cnt8[par][0];
#pragma unroll 4
        for (int u = 0; u < 16; u++) {
            int p = tid + 512 * u;
            float px = pb[3 * p + 0], py = pb[3 * p + 1], pz = pb[3 * p + 2];
            {
                float dx = q0x - px, dy = q0y - py, dz = q0z - pz;
                float d2 = dx * dx + dy * dy + dz * dz;
                if (d2 <= R2C) { int s = atomicAdd(&cntp[0], 1);
                    if (s < CAP) keys4[0 * CAP + s] = ((u64)__float_as_uint(d2) << 32) | (unsigned)p; }
            }
            {
                float dx = q1x - px, dy = q1y - py, dz = q1z - pz;
                float d2 = dx * dx + dy * dy + dz * dz;
                if (d2 <= R2C) { int s = atomicAdd(&cntp[1], 1);
                    if (s < CAP) keys4[1 * CAP + s] = ((u64)__float_as_uint(d2) << 32) | (unsigned)p; }
            }
            {
                float dx = q2x - px, dy = q2y - py, dz = q2z - pz;
                float d2 = dx * dx + dy * dy + dz * dz;
                if (d2 <= R2C) { int s = atomicAdd(&cntp[2], 1);
                    if (s < CAP) keys4[2 * CAP + s] = ((u64)__float_as_uint(d2) << 32) | (unsigned)p; }
            }
            {
                float dx = q3x - px, dy = q3y - py, dz = q3z - pz;
                float d2 = dx * dx + dy * dy + dz * dz;
                if (d2 <= R2C) { int s = atomicAdd(&cntp[3], 1);
                    if (s < CAP) keys4[3 * CAP + s] = ((u64)__float_as_uint(d2) << 32) | (unsigned)p; }
            }
        }
        __syncthreads();                              // B
        if (tid < 4) cnt8[par ^ 1][tid] = 0;          // reset other buffer

        // -------- per centroid: sort + gather + MLP + outputs --------
        for (int cc = 0; cc < 4; cc++) {
            const int c = b * MM + tbase + cc;
            const int n = min(cnt8[par][cc], CAP);
            u64* keyc = keys4 + cc * CAP;

            // register/shfl bitonic sort, 512 keys ascending
            u64 key = (tid < n) ? keyc[tid] : 0xFFFFFFFFFFFFFFFFull;
#pragma unroll
            for (int k2 = 2; k2 <= CAP; k2 <<= 1) {
#pragma unroll
                for (int j = k2 >> 1; j > 0; j >>= 1) {
                    const bool asc = ((tid & k2) == 0);
                    u64 other;
                    if (j >= 32) {
                        __syncthreads();
                        keyc[tid] = key;
                        __syncthreads();
                        other = keyc[tid ^ j];
                    } else {
                        other = shfl_xor64(key, j);
                    }
                    const bool lower = ((tid & j) == 0);
                    const bool keepMin = (lower == asc);
                    const bool less = key < other;
                    key = (less == keepMin) ? key : other;
                }
            }
            __syncthreads();
            keyc[tid] = key;
            __syncthreads();                          // C
            const int m = min(n, KK);

            // gather features (float4)
#pragma unroll
            for (int u = 0; u < 2; u++) {
                int q = tid + 512 * u;                // 0..1023
                int j = q >> 4, c4 = q & 15;
                int row = (j < m) ? (int)(keyc[j] & 0xFFFFFFFFull) : 0;
                float4 vv = xb4[(size_t)row * 16 + c4];
                if (j >= m) { vv.x = 0.0f; vv.y = 0.0f; vv.z = 0.0f; vv.w = 0.0f; }
                *(float4*)&feat[j * 68 + c4 * 4] = vv;
            }
            if (tid < KK) {
                int j = tid;
                int row = (j < m) ? (int)(keyc[j] & 0xFFFFFFFFull) : 0;
                const float* pr = pb + (size_t)row * 3;
                feat[j * 68 + 64] = (j < m) ? pr[0] - qs[cc][0] : 0.0f;
                feat[j * 68 + 65] = (j < m) ? pr[1] - qs[cc][1] : 0.0f;
                feat[j * 68 + 66] = (j < m) ? pr[2] - qs[cc][2] : 0.0f;
                feat[j * 68 + 67] = 0.0f;
            }
            __syncthreads();                          // D

            // phase 1: h1[64,64] = relu(feat @ W1 + b1), FFMA2-packed
            {
                const int rg = tid >> 4;              // rows rg*2, rg*2+1
                const int cg = tid & 15;              // cols cg*4
                float4 bv = *(const float4*)&b1s[cg * 4];
                u64 a0p = pack2(bv.x, bv.y), a0q = pack2(bv.z, bv.w);
                u64 a1p = a0p, a1q = a0q;
                const float* f0p = &feat[(rg * 2 + 0) * 68];
                const float* f1p = &feat[(rg * 2 + 1) * 68];
                for (int k = 0; k < FDIM; k++) {
                    float f0 = f0p[k], f1 = f1p[k];
                    float4 w = *(const float4*)&W1s[k * 64 + cg * 4];
                    u64 w01 = pack2(w.x, w.y), w23 = pack2(w.z, w.w);
                    u64 f0v = pack2(f0, f0), f1v = pack2(f1, f1);
                    a0p = fma2(f0v, w01, a0p); a0q = fma2(f0v, w23, a0q);
                    a1p = fma2(f1v, w01, a1p); a1q = fma2(f1v, w23, a1q);
                }
                float v0, v1, v2, v3;
                float4 h;
                unpack2(a0p, v0, v1); unpack2(a0q, v2, v3);
                h.x = fmaxf(v0, 0.0f); h.y = fmaxf(v1, 0.0f);
                h.z = fmaxf(v2, 0.0f); h.w = fmaxf(v3, 0.0f);
                *(float4*)&h1s[(rg * 2 + 0) * 68 + cg * 4] = h;
                unpack2(a1p, v0, v1); unpack2(a1q, v2, v3);
                h.x = fmaxf(v0, 0.0f); h.y = fmaxf(v1, 0.0f);
                h.z = fmaxf(v2, 0.0f); h.w = fmaxf(v3, 0.0f);
                *(float4*)&h1s[(rg * 2 + 1) * 68 + cg * 4] = h;
            }
            __syncthreads();                          // E

            // phase 2: relu(h1 @ W2 + b2), masked max, FFMA2-packed
            {
                const int rg = tid >> 5;              // rows rg*4..+3
                const int cg = tid & 31;              // cols cg*4
                float4 bv = *(const float4*)&b2s[cg * 4];
                u64 accp[4], accq[4];
#pragma unroll
                for (int r = 0; r < 4; r++) { accp[r] = pack2(bv.x, bv.y); accq[r] = pack2(bv.z, bv.w); }
                for (int k = 0; k < H1D; k++) {
                    float4 w = *(const float4*)&W2s[k * 128 + cg * 4];
                    u64 w01 = pack2(w.x, w.y), w23 = pack2(w.z, w.w);
#pragma unroll
                    for (int r = 0; r < 4; r++) {
                        float hv = h1s[(rg * 4 + r) * 68 + k];
                        u64 hvv = pack2(hv, hv);
                        accp[r] = fma2(hvv, w01, accp[r]);
                        accq[r] = fma2(hvv, w23, accq[r]);
                    }
                }
                float mx0 = -3.402823466e38f, mx1 = mx0, mx2 = mx0, mx3 = mx0;
#pragma unroll
                for (int r = 0; r < 4; r++) {
                    if (rg * 4 + r < m) {
                        float v0, v1, v2, v3;
                        unpack2(accp[r], v0, v1); unpack2(accq[r], v2, v3);
                        mx0 = fmaxf(mx0, fmaxf(v0, 0.0f));
                        mx1 = fmaxf(mx1, fmaxf(v1, 0.0f));
                        mx2 = fmaxf(mx2, fmaxf(v2, 0.0f));
                        mx3 = fmaxf(mx3, fmaxf(v3, 0.0f));
                    }
                }
                float4 mv; mv.x = mx0; mv.y = mx1; mv.z = mx2; mv.w = mx3;
                *(float4*)&pmax[rg * 128 + cg * 4] = mv;
            }
            __syncthreads();                          // F

            if (tid < H2D) {
                float r = pmax[tid];
#pragma unroll
                for (int gg = 1; gg < 16; gg++) r = fmaxf(r, pmax[gg * 128 + tid]);
                if (c * H2D + tid < out_size) out[c * H2D + tid] = r;
            }
            {
                const int PO = BB * MM * H2D;
                const int BO = PO + BB * MM * 3;
                if (tid >= 128 && tid < 131) {
                    int k3 = tid - 128;
                    if (PO + c * 3 + k3 < out_size) out[PO + c * 3 + k3] = qs[cc][k3];
                }
                if (tid == 131 && BO + c < out_size) out[BO + c] = (float)b;
            }
            __syncthreads();                          // G (smem reuse next centroid)
        }
    }
}

// =====================================================================
extern "C" void kernel_launch(void* const* d_in, const int* in_sizes, int n_in,
                              void* d_out, int out_size)
{
    const float* x   = (const float*)d_in[0];
    const float* pos = (const float*)d_in[1];
    const float* W1  = (const float*)d_in[3];
    const float* b1  = (const float*)d_in[4];
    const float* W2  = (const float*)d_in[5];
    const float* b2  = (const float*)d_in[6];
    float* out = (float*)d_out;

    const int FUSED_SMEM = 110080;   // worker layout is the max (keys4 ends at 110080B)
    cudaFuncSetAttribute(fused_kernel, cudaFuncAttributeMaxDynamicSharedMemorySize, FUSED_SMEM);

    reset_kernel<<<1, 32>>>();
    fused_kernel<<<BB + NWORK, 512, FUSED_SMEM>>>(x, pos, W1, b1, W2, b2, out, out_size);
}